// round 2
// baseline (speedup 1.0000x reference)
#include <cuda_runtime.h>
#include <cstdint>

// ============================================================================
// SpectralPoolNd: y = dht2_128( crop_center_128( dht2_256(x) ) )
// dht2(x) = C x (C+S)^T + S x (C-S)^T  (all real, separable)
// Decomposed into 4 GEMM passes over 512 images, 3xTF32 mma.sync for accuracy.
// ============================================================================

#define DI __device__ __forceinline__

// ---- scratch / constant buffers (static device globals; no allocations) ----
__device__ float g_B1[256 * 256];          // pass1 right matrix  [K=256][N=256]
__device__ float g_L1[128 * 512];          // pass2 left matrix   [128][512]
__device__ float g_B2[128 * 256];          // pass3 right matrix  [K=128][N=256]
__device__ float g_L2[128 * 256];          // pass4 left matrix   [128][256]
__device__ float g_T[131072 * 256];        // pass1 out (128MB); reused as U (pass3 out)
__device__ float g_C[512 * 128 * 128];     // pass2 out (32MB)

// ---- constant-matrix generator (exact integer phase reduction) -------------
__global__ void gen_mats_kernel() {
    int i = blockIdx.x * blockDim.x + threadIdx.x;   // 0..65535

    // B1[n][j]: j<128 -> cos+sin at (64+j, n) of 256-DFT ; j>=128 -> cos-sin
    {
        int n = i >> 8, j = i & 255;
        int jj = j & 127;
        float s = (j < 128) ? 1.0f : -1.0f;
        int ph = ((64 + jj) * n) & 255;
        float sn, cs; sincospif((float)ph / 128.0f, &sn, &cs);
        g_B1[i] = cs + s * sn;
    }
    // L1[m][k]: k<256 -> cos(2pi(64+m)k/256) ; k>=256 -> sin(2pi(64+m)(k-256)/256)
    {
        int m = i >> 9, k = i & 511;
        int h = k & 255;
        int ph = ((64 + m) * h) & 255;
        float sn, cs; sincospif((float)ph / 128.0f, &sn, &cs);
        g_L1[i] = (k < 256) ? cs : sn;
    }
    if (i < 32768) {
        // B2[n][j]: 128-point, j<128 -> cos+sin ; j>=128 -> cos-sin
        {
            int n = i >> 8, j = i & 255;
            int jj = j & 127;
            float s = (j < 128) ? 1.0f : -1.0f;
            int ph = (jj * n) & 127;
            float sn, cs; sincospif((float)ph / 64.0f, &sn, &cs);
            g_B2[i] = cs + s * sn;
        }
        // L2[m][k]: k<128 -> cos(2pi m k/128) ; else sin
        {
            int m = i >> 8, k = i & 255;
            int kk = k & 127;
            int ph = (m * kk) & 127;
            float sn, cs; sincospif((float)ph / 64.0f, &sn, &cs);
            g_L2[i] = (k < 128) ? cs : sn;
        }
    }
}

// ---- tf32 helpers ----------------------------------------------------------
DI float tf32r(float x) {
    uint32_t u;
    asm("cvt.rna.tf32.f32 %0, %1;" : "=r"(u) : "f"(x));
    return __uint_as_float(u);
}

DI void mma8(float* d, const uint32_t* a, const uint32_t* b) {
    asm volatile(
        "mma.sync.aligned.m16n8k8.row.col.f32.tf32.tf32.f32 "
        "{%0,%1,%2,%3}, {%4,%5,%6,%7}, {%8,%9}, {%0,%1,%2,%3};\n"
        : "+f"(d[0]), "+f"(d[1]), "+f"(d[2]), "+f"(d[3])
        : "r"(a[0]), "r"(a[1]), "r"(a[2]), "r"(a[3]),
          "r"(b[0]), "r"(b[1]));
}

// ---- 3xTF32 GEMM: C[M,N] (+batch) = A[M,K] * B'  ---------------------------
// B row kappa lives at  B + (kappa % KHALF)*ldb + (kappa / KHALF)*HOFF
// (KHALF == K, HOFF anything -> plain GEMM; pass2/4 use the split-half form)
constexpr int BM = 128, BN = 128, BK = 16;

template <int KHALF, int HOFF>
__global__ __launch_bounds__(256) void gemm3t(
    const float* __restrict__ A, int lda, long long strA,
    const float* __restrict__ B, int ldb, long long strB,
    float* __restrict__ Cc, int ldc, long long strC,
    int K)
{
    __shared__ float shA[2][BM][BK + 1];   // [hi/lo][m][k]
    __shared__ float shB[2][BK][BN + 4];   // [hi/lo][k][n]

    const int tid  = threadIdx.x;
    const int lane = tid & 31;
    const int warp = tid >> 5;
    const int wm = warp & 3;          // 4 warp rows of 32
    const int wn = warp >> 2;         // 2 warp cols of 64
    const int gid = lane >> 2;        // 0..7
    const int tig = lane & 3;         // 0..3

    const long long img = blockIdx.z;
    const float* Ag = A + img * strA;
    const float* Bg = B + img * strB;
    float*       Cg = Cc + img * strC;
    const int m0 = blockIdx.y * BM;
    const int n0 = blockIdx.x * BN;

    float acc[2][8][4];
    #pragma unroll
    for (int mt = 0; mt < 2; mt++)
        #pragma unroll
        for (int nt = 0; nt < 8; nt++)
            #pragma unroll
            for (int q = 0; q < 4; q++) acc[mt][nt][q] = 0.0f;

    for (int k0 = 0; k0 < K; k0 += BK) {
        // load A tile 128x16 (512 float4, 2 per thread), split hi/lo
        #pragma unroll
        for (int r = 0; r < 2; r++) {
            int idx = tid + r * 256;
            int row = idx >> 2;
            int c4  = (idx & 3) * 4;
            const float4 v = *reinterpret_cast<const float4*>(
                Ag + (long long)(m0 + row) * lda + k0 + c4);
            float vv[4] = {v.x, v.y, v.z, v.w};
            #pragma unroll
            for (int e = 0; e < 4; e++) {
                float hi = tf32r(vv[e]);
                shA[0][row][c4 + e] = hi;
                shA[1][row][c4 + e] = tf32r(vv[e] - hi);
            }
        }
        // load B tile 16x128 (512 float4, 2 per thread), split hi/lo
        #pragma unroll
        for (int r = 0; r < 2; r++) {
            int idx = tid + r * 256;
            int row = idx >> 5;
            int c4  = (idx & 31) * 4;
            int kap = k0 + row;
            long long off = (long long)(kap % KHALF) * ldb + (long long)(kap / KHALF) * HOFF;
            const float4 v = *reinterpret_cast<const float4*>(Bg + off + n0 + c4);
            float vv[4] = {v.x, v.y, v.z, v.w};
            #pragma unroll
            for (int e = 0; e < 4; e++) {
                float hi = tf32r(vv[e]);
                shB[0][row][c4 + e] = hi;
                shB[1][row][c4 + e] = tf32r(vv[e] - hi);
            }
        }
        __syncthreads();

        #pragma unroll
        for (int kk = 0; kk < BK; kk += 8) {
            uint32_t aH[2][4], aL[2][4];
            #pragma unroll
            for (int mt = 0; mt < 2; mt++) {
                int rbase = wm * 32 + mt * 16;
                #pragma unroll
                for (int q = 0; q < 4; q++) {
                    int rr = rbase + gid + (q & 1) * 8;
                    int cc = kk + tig + (q >> 1) * 4;
                    aH[mt][q] = __float_as_uint(shA[0][rr][cc]);
                    aL[mt][q] = __float_as_uint(shA[1][rr][cc]);
                }
            }
            #pragma unroll
            for (int nt = 0; nt < 8; nt++) {
                int cb = wn * 64 + nt * 8 + gid;
                uint32_t bH[2], bL[2];
                bH[0] = __float_as_uint(shB[0][kk + tig][cb]);
                bH[1] = __float_as_uint(shB[0][kk + tig + 4][cb]);
                bL[0] = __float_as_uint(shB[1][kk + tig][cb]);
                bL[1] = __float_as_uint(shB[1][kk + tig + 4][cb]);
                #pragma unroll
                for (int mt = 0; mt < 2; mt++) {
                    mma8(acc[mt][nt], aH[mt], bH);   // hi*hi
                    mma8(acc[mt][nt], aH[mt], bL);   // hi*lo
                    mma8(acc[mt][nt], aL[mt], bH);   // lo*hi
                }
            }
        }
        __syncthreads();
    }

    // epilogue: float2 stores
    #pragma unroll
    for (int mt = 0; mt < 2; mt++) {
        #pragma unroll
        for (int nt = 0; nt < 8; nt++) {
            int row = m0 + wm * 32 + mt * 16 + gid;
            int col = n0 + wn * 64 + nt * 8 + tig * 2;
            float2 lo = make_float2(acc[mt][nt][0], acc[mt][nt][1]);
            float2 hi = make_float2(acc[mt][nt][2], acc[mt][nt][3]);
            *reinterpret_cast<float2*>(Cg + (long long)row * ldc + col) = lo;
            *reinterpret_cast<float2*>(Cg + (long long)(row + 8) * ldc + col) = hi;
        }
    }
}

// ---- launcher --------------------------------------------------------------
extern "C" void kernel_launch(void* const* d_in, const int* in_sizes, int n_in,
                              void* d_out, int out_size)
{
    const float* x  = (const float*)d_in[0];   // (8,64,256,256) = 131072 x 256
    float*       out = (float*)d_out;          // (8,64,128,128) = 512 x 128 x 128

    void *pB1, *pL1, *pB2, *pL2, *pT, *pC;
    cudaGetSymbolAddress(&pB1, g_B1);
    cudaGetSymbolAddress(&pL1, g_L1);
    cudaGetSymbolAddress(&pB2, g_B2);
    cudaGetSymbolAddress(&pL2, g_L2);
    cudaGetSymbolAddress(&pT,  g_T);
    cudaGetSymbolAddress(&pC,  g_C);
    float* B1 = (float*)pB1; float* L1 = (float*)pL1;
    float* B2 = (float*)pB2; float* L2 = (float*)pL2;
    float* T  = (float*)pT;  float* Cm = (float*)pC;

    // constants (cheap; recomputed every call -> deterministic, capture-safe)
    gen_mats_kernel<<<256, 256>>>();

    // pass1: T[131072 x 256] = X * B1           (W contraction, stage 1)
    gemm3t<256, 0><<<dim3(2, 1024, 1), 256>>>(
        x, 256, 0LL, B1, 256, 0LL, T, 256, 0LL, 256);

    // pass2: c_i[128 x 128] = [A|As] * [t1;t2]  (H contraction, stage 1), 512 imgs
    gemm3t<256, 128><<<dim3(1, 1, 512), 256>>>(
        L1, 512, 0LL, T, 256, 65536LL, Cm, 128, 16384LL, 512);

    // pass3: U[65536 x 256] = c * B2            (W contraction, stage 2), U aliases T
    gemm3t<128, 0><<<dim3(2, 512, 1), 256>>>(
        Cm, 128, 0LL, B2, 256, 0LL, T, 256, 0LL, 128);

    // pass4: y_i[128 x 128] = [C2|S2] * [u1;u2] (H contraction, stage 2), 512 imgs
    gemm3t<128, 128><<<dim3(1, 1, 512), 256>>>(
        L2, 256, 0LL, T, 256, 32768LL, out, 128, 16384LL, 256);
}

// round 8
// speedup vs baseline: 2.1119x; 2.1119x over previous
#include <cuda_runtime.h>
#include <cuda_bf16.h>
#include <cstdint>

#define DI __device__ __forceinline__

// ============================================================================
// SpectralPoolNd: y = dht2_128( crop_center_128( dht2_256(x) ) )
// 4 GEMM passes over 512 images; 3xBF16 split on mma.sync.m16n8k16 (sm_103
// legacy tensor pipe), ldmatrix fragment feed, double-buffered smem tiles.
// ============================================================================

// ---------------- device buffers (no allocations) ----------------
__device__ float g_B1t[256 * 256];        // pass1 B^T  [N=256 rows][K=256]
__device__ float g_L1 [128 * 512];        // pass2 A    [128][512]
__device__ float g_B2t[256 * 128];        // pass3 B^T  [N=256 rows][K=128]
__device__ float g_L2 [128 * 256];        // pass4 A    [128][256]
__device__ float g_T  [512 * 256 * 256];  // T_t [img][j][h]; aliased as U_t [img][256][128]
__device__ float g_Cm [512 * 128 * 128];  // c   [img][m][n]

// ---------------- constant generator (exact integer phases) ----------------
__global__ void gen_mats() {
    int i = blockIdx.x * blockDim.x + threadIdx.x;   // 0..65535
    {   // B1t[j][n] = cas_s(j)((64+(j&127)) * n), 256-pt
        int j = i >> 8, n = i & 255;
        int jj = j & 127;
        float s = (j < 128) ? 1.0f : -1.0f;
        int ph = ((64 + jj) * n) & 255;
        float sn, cs; sincospif((float)ph / 128.0f, &sn, &cs);
        g_B1t[i] = cs + s * sn;
    }
    {   // L1[m][k]: k<256 cos((64+m)k), else sin((64+m)(k-256)), 256-pt
        int m = i >> 9, k = i & 511;
        int ph = ((64 + m) * (k & 255)) & 255;
        float sn, cs; sincospif((float)ph / 128.0f, &sn, &cs);
        g_L1[i] = (k < 256) ? cs : sn;
    }
    if (i < 32768) {
        {   // B2t[j][n] = cas_s(j)((j&127) * n), 128-pt ; [256 rows][128]
            int j = i >> 7, n = i & 127;
            int jj = j & 127;
            float s = (j < 128) ? 1.0f : -1.0f;
            int ph = (jj * n) & 127;
            float sn, cs; sincospif((float)ph / 64.0f, &sn, &cs);
            g_B2t[i] = cs + s * sn;
        }
        {   // L2[m][k]: k<128 cos(mk), else sin(m(k-128)), 128-pt
            int m = i >> 8, k = i & 255;
            int ph = (m * (k & 127)) & 127;
            float sn, cs; sincospif((float)ph / 64.0f, &sn, &cs);
            g_L2[i] = (k < 128) ? cs : sn;
        }
    }
}

// ---------------- helpers ----------------
DI uint32_t smem_u32(const void* p) {
    uint32_t a;
    asm("{ .reg .u64 t; cvta.to.shared.u64 t, %1; cvt.u32.u64 %0, t; }"
        : "=r"(a) : "l"(p));
    return a;
}

DI uint32_t pk2(float a, float b) {
    __nv_bfloat162 t = __floats2bfloat162_rn(a, b);
    return *reinterpret_cast<uint32_t*>(&t);
}

// split 8 f32 into bf16 hi (16B) + bf16 lo (16B)
DI void split8(const float4 v0, const float4 v1, uint4& H, uint4& L) {
    float e[8] = {v0.x, v0.y, v0.z, v0.w, v1.x, v1.y, v1.z, v1.w};
    float h[8], l[8];
    #pragma unroll
    for (int i = 0; i < 8; i++) {
        __nv_bfloat16 hb = __float2bfloat16_rn(e[i]);
        h[i] = __bfloat162float(hb);
        l[i] = e[i] - h[i];
    }
    H.x = pk2(h[0], h[1]); H.y = pk2(h[2], h[3]);
    H.z = pk2(h[4], h[5]); H.w = pk2(h[6], h[7]);
    L.x = pk2(l[0], l[1]); L.y = pk2(l[2], l[3]);
    L.z = pk2(l[4], l[5]); L.w = pk2(l[6], l[7]);
}

// tile: 128 rows x 32 bf16 (64B row = 4 x 16B chunks), XOR swizzle for
// conflict-free ldmatrix (8 consecutive rows distinct mod 128B)
DI uint32_t swz(int row, int kc) {
    return (uint32_t)(row * 64 + ((kc ^ ((row >> 1) & 3)) << 4));
}

constexpr int AH_OFF = 0, AL_OFF = 8192, BH_OFF = 16384, BL_OFF = 24576;
constexpr int STAGE = 32768;
constexpr int SMEM_BYTES = 128 * 132 * 4;   // 67584 >= 2*STAGE, holds epilogue D

DI void mma16(float* d, const uint32_t* a, uint32_t b0, uint32_t b1) {
    asm volatile(
        "mma.sync.aligned.m16n8k16.row.col.f32.bf16.bf16.f32 "
        "{%0,%1,%2,%3}, {%4,%5,%6,%7}, {%8,%9}, {%0,%1,%2,%3};\n"
        : "+f"(d[0]), "+f"(d[1]), "+f"(d[2]), "+f"(d[3])
        : "r"(a[0]), "r"(a[1]), "r"(a[2]), "r"(a[3]), "r"(b0), "r"(b1));
}

#define LDSM4(R, A)                                                            \
    asm volatile("ldmatrix.sync.aligned.m8n8.x4.shared.b16 {%0,%1,%2,%3}, [%4];" \
                 : "=r"((R)[0]), "=r"((R)[1]), "=r"((R)[2]), "=r"((R)[3])      \
                 : "r"(A))

// ---------------- main pass kernel ----------------
// C[128 x 128] (+grid tiling) = A[.,K] * B'[.,K]^T, both operands K-major.
template <int PASS, int KTOT>
__global__ __launch_bounds__(256) void dht_pass(
    const float* __restrict__ A0, const float* __restrict__ B0, float* __restrict__ O0)
{
    extern __shared__ char smem[];
    const uint32_t sbu = smem_u32(smem);
    const int tid  = threadIdx.x;
    const int lane = tid & 31, warp = tid >> 5;
    const int wm = warp & 3, wn = warp >> 2;
    constexpr int NT  = KTOT / 32;
    constexpr int LDA = (PASS == 1) ? 256 : (PASS == 2) ? 512 : (PASS == 3) ? 128 : 256;
    constexpr int LDB = (PASS <= 2) ? 256 : 128;

    const int n0 = blockIdx.x * 128;
    const float* Ag; const float* Bg; float* Og;
    int h0 = 0;
    if (PASS == 1) {
        const int m0 = blockIdx.y * 128;
        Ag = A0 + (long long)m0 * 256;
        Bg = B0 + (long long)n0 * 256;
        Og = O0 + (long long)(m0 >> 8) * 65536;
        h0 = m0 & 255;
    } else if (PASS == 2) {
        Ag = A0;
        Bg = B0 + (long long)blockIdx.z * 65536;
        Og = O0 + (long long)blockIdx.z * 16384;
    } else if (PASS == 3) {
        Ag = A0 + (long long)blockIdx.z * 16384;
        Bg = B0 + (long long)n0 * 128;
        Og = O0 + (long long)blockIdx.z * 32768;
    } else {
        Ag = A0;
        Bg = B0 + (long long)blockIdx.z * 32768;
        Og = O0 + (long long)blockIdx.z * 16384;
    }

    // per-thread fill coords: 2 A-chunks + 2 B-chunks of 8 f32 each
    const int ra0 = tid >> 2;        // row of first chunk (second = +64)
    const int ka0 = tid & 3;         // 16B-chunk index within 64B row

    float4 R[8];
    auto ldg = [&](int k0) {
        long long bb;
        if      (PASS == 1 || PASS == 3) bb = k0;
        else if (PASS == 2) bb = (long long)(k0 >> 8) * 32768 + (k0 & 255);
        else                bb = (long long)(k0 >> 7) * 16384 + (k0 & 127);
        #pragma unroll
        for (int i = 0; i < 2; i++) {
            const float* p = Ag + (long long)(ra0 + i * 64) * LDA + k0 + ka0 * 8;
            R[i * 2 + 0] = *(const float4*)p;
            R[i * 2 + 1] = *(const float4*)(p + 4);
        }
        #pragma unroll
        for (int i = 0; i < 2; i++) {
            const float* p = Bg + bb + (long long)(ra0 + i * 64) * LDB + ka0 * 8;
            R[4 + i * 2] = *(const float4*)p;
            R[5 + i * 2] = *(const float4*)(p + 4);
        }
    };

    auto cvt_sts = [&](int buf) {
        char* sb = smem + buf * STAGE;
        #pragma unroll
        for (int i = 0; i < 2; i++) {
            const uint32_t off = swz(ra0 + i * 64, ka0);
            uint4 H, L;
            split8(R[i * 2], R[i * 2 + 1], H, L);
            *(uint4*)(sb + AH_OFF + off) = H;
            *(uint4*)(sb + AL_OFF + off) = L;
            split8(R[4 + i * 2], R[5 + i * 2], H, L);
            *(uint4*)(sb + BH_OFF + off) = H;
            *(uint4*)(sb + BL_OFF + off) = L;
        }
    };

    float acc[2][8][4];
    #pragma unroll
    for (int mt = 0; mt < 2; mt++)
        #pragma unroll
        for (int nt = 0; nt < 8; nt++)
            #pragma unroll
            for (int q = 0; q < 4; q++) acc[mt][nt][q] = 0.0f;

    auto compute = [&](int buf) {
        const uint32_t sbase = sbu + buf * STAGE;
        #pragma unroll
        for (int kk = 0; kk < 32; kk += 16) {
            const int c0 = kk >> 3;
            uint32_t aH[2][4], aL[2][4];
            #pragma unroll
            for (int mt = 0; mt < 2; mt++) {
                const int row = wm * 32 + mt * 16 + (lane & 15);
                const int ch  = c0 + (lane >> 4);
                const uint32_t off = swz(row, ch);
                LDSM4(aH[mt], sbase + AH_OFF + off);
                LDSM4(aL[mt], sbase + AL_OFF + off);
            }
            #pragma unroll
            for (int nt = 0; nt < 4; nt++) {
                const int nrow = wn * 64 + nt * 16 + (lane & 7) + ((lane >> 4) << 3);
                const int ch   = c0 + ((lane >> 3) & 1);
                const uint32_t off = swz(nrow, ch);
                uint32_t bh[4], bl[4];
                LDSM4(bh, sbase + BH_OFF + off);
                LDSM4(bl, sbase + BL_OFF + off);
                #pragma unroll
                for (int mt = 0; mt < 2; mt++) {
                    mma16(acc[mt][nt * 2],     aH[mt], bh[0], bh[1]);
                    mma16(acc[mt][nt * 2],     aH[mt], bl[0], bl[1]);
                    mma16(acc[mt][nt * 2],     aL[mt], bh[0], bh[1]);
                    mma16(acc[mt][nt * 2 + 1], aH[mt], bh[2], bh[3]);
                    mma16(acc[mt][nt * 2 + 1], aH[mt], bl[2], bl[3]);
                    mma16(acc[mt][nt * 2 + 1], aL[mt], bh[2], bh[3]);
                }
            }
        }
    };

    // ---- pipelined main loop: one barrier per K-tile ----
    ldg(0);
    #pragma unroll 1
    for (int t = 0; t < NT; t++) {
        cvt_sts(t & 1);
        __syncthreads();
        if (t + 1 < NT) ldg((t + 1) * 32);
        compute(t & 1);
    }
    __syncthreads();

    // ---- epilogue ----
    if (PASS == 1 || PASS == 3) {
        // transposed store via smem: D[j][m] padded rows of 132 f32
        constexpr int OST = (PASS == 1) ? 256 : 128;
        float* Ds = (float*)smem;
        #pragma unroll
        for (int mt = 0; mt < 2; mt++)
            #pragma unroll
            for (int nt = 0; nt < 8; nt++) {
                const int m = wm * 32 + mt * 16 + (lane >> 2);
                const int j = wn * 64 + nt * 8 + 2 * (lane & 3);
                Ds[j * 132 + m]           = acc[mt][nt][0];
                Ds[(j + 1) * 132 + m]     = acc[mt][nt][1];
                Ds[j * 132 + m + 8]       = acc[mt][nt][2];
                Ds[(j + 1) * 132 + m + 8] = acc[mt][nt][3];
            }
        __syncthreads();
        #pragma unroll 1
        for (int it = 0; it < 16; it++) {
            const int flat = it * 256 + tid;
            const int j = flat >> 5, mq = (flat & 31) * 4;
            const float4 v = *(const float4*)&Ds[j * 132 + mq];
            *(float4*)&Og[(long long)(n0 + j) * OST + h0 + mq] = v;
        }
    } else {
        // row-major direct store
        #pragma unroll
        for (int mt = 0; mt < 2; mt++)
            #pragma unroll
            for (int nt = 0; nt < 8; nt++) {
                const int m = wm * 32 + mt * 16 + (lane >> 2);
                const int n = wn * 64 + nt * 8 + 2 * (lane & 3);
                *(float2*)&Og[(long long)m * 128 + n] =
                    make_float2(acc[mt][nt][0], acc[mt][nt][1]);
                *(float2*)&Og[(long long)(m + 8) * 128 + n] =
                    make_float2(acc[mt][nt][2], acc[mt][nt][3]);
            }
    }
}

// ---------------- launcher ----------------
extern "C" void kernel_launch(void* const* d_in, const int* in_sizes, int n_in,
                              void* d_out, int out_size)
{
    (void)in_sizes; (void)n_in; (void)out_size;
    const float* x = (const float*)d_in[0];     // (8,64,256,256)
    float* out     = (float*)d_out;             // (8,64,128,128)

    void *pB1, *pL1, *pB2, *pL2, *pT, *pC;
    cudaGetSymbolAddress(&pB1, g_B1t);
    cudaGetSymbolAddress(&pL1, g_L1);
    cudaGetSymbolAddress(&pB2, g_B2t);
    cudaGetSymbolAddress(&pL2, g_L2);
    cudaGetSymbolAddress(&pT,  g_T);
    cudaGetSymbolAddress(&pC,  g_Cm);
    float* B1t = (float*)pB1; float* L1 = (float*)pL1;
    float* B2t = (float*)pB2; float* L2 = (float*)pL2;
    float* T   = (float*)pT;  float* Cm = (float*)pC;
    float* U   = T;  // alias: T dead after pass2

    cudaFuncSetAttribute(dht_pass<1, 256>, cudaFuncAttributeMaxDynamicSharedMemorySize, SMEM_BYTES);
    cudaFuncSetAttribute(dht_pass<2, 512>, cudaFuncAttributeMaxDynamicSharedMemorySize, SMEM_BYTES);
    cudaFuncSetAttribute(dht_pass<3, 128>, cudaFuncAttributeMaxDynamicSharedMemorySize, SMEM_BYTES);
    cudaFuncSetAttribute(dht_pass<4, 256>, cudaFuncAttributeMaxDynamicSharedMemorySize, SMEM_BYTES);

    gen_mats<<<256, 256>>>();

    // pass1: T_t[img][j][h] = (X * B1t^T)^T        M=131072, N=256, K=256
    dht_pass<1, 256><<<dim3(2, 1024, 1), 256, SMEM_BYTES>>>(x, B1t, T);
    // pass2: c[img][m][n] = L1 * Tsplit            M=128, N=128, K=512 per img
    dht_pass<2, 512><<<dim3(1, 1, 512), 256, SMEM_BYTES>>>(L1, T, Cm);
    // pass3: U_t[img][j][m] = (c * B2t^T)^T        M=128, N=256, K=128 per img
    dht_pass<3, 128><<<dim3(2, 1, 512), 256, SMEM_BYTES>>>(Cm, B2t, U);
    // pass4: y[img][m][n] = L2 * Usplit            M=128, N=128, K=256 per img
    dht_pass<4, 256><<<dim3(1, 1, 512), 256, SMEM_BYTES>>>(L2, U, out);
}

// round 9
// speedup vs baseline: 2.2051x; 1.0441x over previous
#include <cuda_runtime.h>
#include <cuda_bf16.h>
#include <cstdint>

#define DI __device__ __forceinline__

// ============================================================================
// SpectralPoolNd: y = dht2_128( crop_center_128( dht2_256(x) ) )
// All operands pre-split into bf16 hi/lo in swizzled 32-K tile format.
// 4 GEMM passes, pure cp.async fills, 3-stage pipeline, 2 CTAs/SM.
// ============================================================================

// Tile format: one K-chunk (32 k-values) of a 128-row operand = 16 KB:
//   [hi 8192 B][lo 8192 B], element (row, col) chunk addr = swz(row, col>>3),
//   byte within chunk = (col&7)*2.
DI uint32_t swz(int row, int kc) {
    return (uint32_t)(row * 64 + ((kc ^ ((row >> 1) & 3)) << 4));
}

// ---------------- device buffers (no allocations) ----------------
__device__ __align__(16) char g_B1c[2 * 8 * 16384];    // pass1 B tiles [nb][t]
__device__ __align__(16) char g_L1c[16 * 16384];       // pass2 A tiles [t]
__device__ __align__(16) char g_B2c[2 * 4 * 16384];    // pass3 B tiles [nb][t]
__device__ __align__(16) char g_L2c[8 * 16384];        // pass4 A tiles [t]
__device__ __align__(16) char g_Xb [1024 * 8 * 16384]; // x tiles [mb][t]   128MB
__device__ __align__(16) char g_Tb [512 * 16 * 16384]; // T tiles [img][t]  128MB (U aliases)
__device__ __align__(16) char g_Cb [512 * 4 * 16384];  // c tiles [img][t]   32MB

// ---------------- split helpers ----------------
DI uint32_t pk2(float a, float b) {
    __nv_bfloat162 t = __floats2bfloat162_rn(a, b);
    return *reinterpret_cast<uint32_t*>(&t);
}
DI void split8(const float4 v0, const float4 v1, uint4& H, uint4& L) {
    float e[8] = {v0.x, v0.y, v0.z, v0.w, v1.x, v1.y, v1.z, v1.w};
    float h[8], l[8];
    #pragma unroll
    for (int i = 0; i < 8; i++) {
        __nv_bfloat16 hb = __float2bfloat16_rn(e[i]);
        h[i] = __bfloat162float(hb);
        l[i] = e[i] - h[i];
    }
    H.x = pk2(h[0], h[1]); H.y = pk2(h[2], h[3]);
    H.z = pk2(h[4], h[5]); H.w = pk2(h[6], h[7]);
    L.x = pk2(l[0], l[1]); L.y = pk2(l[2], l[3]);
    L.z = pk2(l[4], l[5]); L.w = pk2(l[6], l[7]);
}

// ---------------- constant generator (exact integer phases) ----------------
__global__ void gen_consts() {
    int e = blockIdx.x * 256 + threadIdx.x;      // 0..196607
    float v; char* base; int row, col;
    if (e < 65536) {                             // B1c: [nb 2][t 8][row 128][col 32]
        int nb = e >> 15, r = e & 32767;
        int tile = r >> 12, rem = r & 4095; row = rem >> 5; col = rem & 31;
        int j = nb * 128 + row, k = tile * 32 + col;
        int jj = j & 127; float s = (j < 128) ? 1.f : -1.f;
        int ph = ((64 + jj) * k) & 255;
        float sn, cs; sincospif((float)ph / 128.f, &sn, &cs);
        v = cs + s * sn;
        base = g_B1c + (size_t)(nb * 8 + tile) * 16384;
    } else if (e < 131072) {                     // L1c: [t 16][row 128][col 32]
        int r = e - 65536;
        int tile = r >> 12, rem = r & 4095; row = rem >> 5; col = rem & 31;
        int kap = tile * 32 + col;
        int ph = ((64 + row) * (kap & 255)) & 255;
        float sn, cs; sincospif((float)ph / 128.f, &sn, &cs);
        v = (kap < 256) ? cs : sn;
        base = g_L1c + (size_t)tile * 16384;
    } else if (e < 163840) {                     // B2c: [nb 2][t 4][128][32]
        int r = e - 131072;
        int nb = r >> 14, r2 = r & 16383;
        int tile = r2 >> 12, rem = r2 & 4095; row = rem >> 5; col = rem & 31;
        int j = nb * 128 + row, k = tile * 32 + col;
        int jj = j & 127; float s = (j < 128) ? 1.f : -1.f;
        int ph = (jj * k) & 127;
        float sn, cs; sincospif((float)ph / 64.f, &sn, &cs);
        v = cs + s * sn;
        base = g_B2c + (size_t)(nb * 4 + tile) * 16384;
    } else {                                     // L2c: [t 8][128][32]
        int r = e - 163840;
        int tile = r >> 12, rem = r & 4095; row = rem >> 5; col = rem & 31;
        int k = tile * 32 + col;
        int ph = (row * (k & 127)) & 127;
        float sn, cs; sincospif((float)ph / 64.f, &sn, &cs);
        v = (k < 128) ? cs : sn;
        base = g_L2c + (size_t)tile * 16384;
    }
    __nv_bfloat16 hb = __float2bfloat16_rn(v);
    float hf = __bfloat162float(hb);
    __nv_bfloat16 lb = __float2bfloat16_rn(v - hf);
    char* p = base + swz(row, col >> 3) + (col & 7) * 2;
    *(__nv_bfloat16*)p = hb;
    *(__nv_bfloat16*)(p + 8192) = lb;
}

// ---------------- input converter: x (f32) -> split tiles ----------------
__global__ void cvt_x(const float* __restrict__ x) {
    int id = blockIdx.x * 256 + threadIdx.x;     // 0..4194303 chunk ids
    int kc = id & 3, row = (id >> 2) & 127, tile = id >> 9;   // tile 0..8191
    int mb = tile >> 3, t = tile & 7;
    const float* p = x + (size_t)(mb * 128 + row) * 256 + t * 32 + kc * 8;
    float4 v0 = *(const float4*)p, v1 = *(const float4*)(p + 4);
    uint4 H, L; split8(v0, v1, H, L);
    char* g = g_Xb + (size_t)tile * 16384 + swz(row, kc);
    *(uint4*)g = H;
    *(uint4*)(g + 8192) = L;
}

// ---------------- PTX ----------------
DI uint32_t smem_u32(const void* p) {
    uint32_t a;
    asm("{ .reg .u64 t; cvta.to.shared.u64 t, %1; cvt.u32.u64 %0, t; }"
        : "=r"(a) : "l"(p));
    return a;
}
#define CP_A16(dst, src)                                                       \
    asm volatile("cp.async.cg.shared.global [%0], [%1], 16;"                   \
                 :: "r"(dst), "l"(src))
#define CP_COMMIT() asm volatile("cp.async.commit_group;" ::: "memory")
#define CP_WAIT1()  asm volatile("cp.async.wait_group 1;" ::: "memory")
#define CP_WAIT0()  asm volatile("cp.async.wait_group 0;" ::: "memory")

DI void mma16(float* d, const uint32_t* a, uint32_t b0, uint32_t b1) {
    asm volatile(
        "mma.sync.aligned.m16n8k16.row.col.f32.bf16.bf16.f32 "
        "{%0,%1,%2,%3}, {%4,%5,%6,%7}, {%8,%9}, {%0,%1,%2,%3};\n"
        : "+f"(d[0]), "+f"(d[1]), "+f"(d[2]), "+f"(d[3])
        : "r"(a[0]), "r"(a[1]), "r"(a[2]), "r"(a[3]), "r"(b0), "r"(b1));
}
#define LDSM4(R, A)                                                            \
    asm volatile("ldmatrix.sync.aligned.m8n8.x4.shared.b16 {%0,%1,%2,%3}, [%4];" \
                 : "=r"((R)[0]), "=r"((R)[1]), "=r"((R)[2]), "=r"((R)[3])      \
                 : "r"(A))

// smem: 3 stages x 32KB: [AH 8K][AL 8K][BH 8K][BL 8K]; epilogue staging reuses.
constexpr int STAGE = 32768;
constexpr int SMEM_BYTES = 3 * STAGE;

DI void fill_cp(uint32_t sdst, const char* __restrict__ sA,
                const char* __restrict__ sB, int tid) {
    const uint32_t o = (uint32_t)tid * 64;       // 256 thr x 64B = 16KB/operand
    #pragma unroll
    for (int i = 0; i < 4; i++) CP_A16(sdst + o + i * 16, sA + o + i * 16);
    #pragma unroll
    for (int i = 0; i < 4; i++) CP_A16(sdst + 16384 + o + i * 16, sB + o + i * 16);
}

// emit a 128x128 f32 block (smem, stride 132) as 4 split-swizzled tiles
DI void emit_tiles(const float* __restrict__ Ds, char* __restrict__ gbase, int tid) {
    #pragma unroll 1
    for (int it = 0; it < 8; it++) {
        int c = it * 256 + tid;                  // 0..2047 chunk ids
        int r = c >> 4, cc = c & 15, tt = cc >> 2, kc = cc & 3;
        const float* p = Ds + r * 132 + cc * 8;
        float4 v0 = *(const float4*)p, v1 = *(const float4*)(p + 4);
        uint4 H, L; split8(v0, v1, H, L);
        char* g = gbase + tt * 16384 + swz(r, kc);
        *(uint4*)g = H;
        *(uint4*)(g + 8192) = L;
    }
}

// ---------------- main pass kernel ----------------
// C[128x128] = A[128,K] * B[128,K]^T, operands as split tiles; 3x bf16 MMA.
template <int PASS, int KTOT>
__global__ __launch_bounds__(256, 2) void dht_pass(
    const char* __restrict__ Asrc, const char* __restrict__ Bsrc,
    char* __restrict__ Ob, float* __restrict__ O0)
{
    extern __shared__ char smem[];
    const uint32_t sbu = smem_u32(smem);
    const int tid = threadIdx.x;
    const int lane = tid & 31, warp = tid >> 5;
    const int wm = warp & 3, wn = warp >> 2;
    constexpr int NT = KTOT / 32;

    const char* Ab; const char* Bb;
    char* Eb = nullptr; float* Eo = nullptr;
    if (PASS == 1) {
        const int mb = blockIdx.y, nb = blockIdx.x;
        Ab = Asrc + (size_t)mb * 131072;
        Bb = Bsrc + (size_t)nb * 131072;
        Eb = Ob + (size_t)(mb >> 1) * 262144 + (size_t)(nb * 8 + (mb & 1) * 4) * 16384;
    } else if (PASS == 2) {
        Ab = Asrc;
        Bb = Bsrc + (size_t)blockIdx.z * 262144;
        Eb = Ob + (size_t)blockIdx.z * 65536;
    } else if (PASS == 3) {
        const int nb = blockIdx.x;
        Ab = Asrc + (size_t)blockIdx.z * 65536;
        Bb = Bsrc + (size_t)nb * 65536;
        Eb = Ob + (size_t)blockIdx.z * 131072 + (size_t)nb * 65536;
    } else {
        Ab = Asrc;
        Bb = Bsrc + (size_t)blockIdx.z * 131072;
        Eo = O0 + (size_t)blockIdx.z * 16384;
    }

    float acc[2][8][4];
    #pragma unroll
    for (int mt = 0; mt < 2; mt++)
        #pragma unroll
        for (int nt = 0; nt < 8; nt++)
            #pragma unroll
            for (int q = 0; q < 4; q++) acc[mt][nt][q] = 0.0f;

    auto compute = [&](uint32_t sbase) {
        #pragma unroll
        for (int kk = 0; kk < 32; kk += 16) {
            const int c0 = kk >> 3;
            uint32_t aH[2][4], aL[2][4];
            #pragma unroll
            for (int mt = 0; mt < 2; mt++) {
                const int row = wm * 32 + mt * 16 + (lane & 15);
                const int ch  = c0 + (lane >> 4);
                const uint32_t off = swz(row, ch);
                LDSM4(aH[mt], sbase + off);
                LDSM4(aL[mt], sbase + 8192 + off);
            }
            #pragma unroll
            for (int nt = 0; nt < 4; nt++) {
                const int nrow = wn * 64 + nt * 16 + (lane & 7) + ((lane >> 4) << 3);
                const int ch   = c0 + ((lane >> 3) & 1);
                const uint32_t off = swz(nrow, ch);
                uint32_t bh[4], bl[4];
                LDSM4(bh, sbase + 16384 + off);
                LDSM4(bl, sbase + 24576 + off);
                #pragma unroll
                for (int mt = 0; mt < 2; mt++) {
                    mma16(acc[mt][nt * 2],     aH[mt], bh[0], bh[1]);
                    mma16(acc[mt][nt * 2],     aH[mt], bl[0], bl[1]);
                    mma16(acc[mt][nt * 2],     aL[mt], bh[0], bh[1]);
                    mma16(acc[mt][nt * 2 + 1], aH[mt], bh[2], bh[3]);
                    mma16(acc[mt][nt * 2 + 1], aH[mt], bl[2], bl[3]);
                    mma16(acc[mt][nt * 2 + 1], aL[mt], bh[2], bh[3]);
                }
            }
        }
    };

    // ---- 3-stage cp.async pipeline, one barrier per K-tile ----
    fill_cp(sbu,         Ab,         Bb,         tid); CP_COMMIT();
    fill_cp(sbu + STAGE, Ab + 16384, Bb + 16384, tid); CP_COMMIT();
    #pragma unroll 1
    for (int t = 0; t < NT; t++) {
        if (t + 1 < NT) { CP_WAIT1(); } else { CP_WAIT0(); }
        __syncthreads();
        if (t + 2 < NT) {
            const int s = (t + 2) % 3;
            fill_cp(sbu + s * STAGE, Ab + (size_t)(t + 2) * 16384,
                    Bb + (size_t)(t + 2) * 16384, tid);
            CP_COMMIT();
        }
        compute(sbu + (t % 3) * STAGE);
    }
    __syncthreads();

    // ---- epilogue ----
    if (PASS == 4) {
        // direct f32 row-major store to d_out
        #pragma unroll
        for (int mt = 0; mt < 2; mt++)
            #pragma unroll
            for (int nt = 0; nt < 8; nt++) {
                const int m = wm * 32 + mt * 16 + (lane >> 2);
                const int n = wn * 64 + nt * 8 + 2 * (lane & 3);
                *(float2*)&Eo[(size_t)m * 128 + n] =
                    make_float2(acc[mt][nt][0], acc[mt][nt][1]);
                *(float2*)&Eo[(size_t)(m + 8) * 128 + n] =
                    make_float2(acc[mt][nt][2], acc[mt][nt][3]);
            }
    } else {
        float* Ds = (float*)smem;
        if (PASS == 2) {
            // untransposed staging D[m][n]
            #pragma unroll
            for (int mt = 0; mt < 2; mt++)
                #pragma unroll
                for (int nt = 0; nt < 8; nt++) {
                    const int m = wm * 32 + mt * 16 + (lane >> 2);
                    const int n = wn * 64 + nt * 8 + 2 * (lane & 3);
                    *(float2*)&Ds[m * 132 + n] =
                        make_float2(acc[mt][nt][0], acc[mt][nt][1]);
                    *(float2*)&Ds[(m + 8) * 132 + n] =
                        make_float2(acc[mt][nt][2], acc[mt][nt][3]);
                }
        } else {
            // transposed staging D[j][m]  (j = output row of T_t/U_t)
            #pragma unroll
            for (int mt = 0; mt < 2; mt++)
                #pragma unroll
                for (int nt = 0; nt < 8; nt++) {
                    const int m = wm * 32 + mt * 16 + (lane >> 2);
                    const int j = wn * 64 + nt * 8 + 2 * (lane & 3);
                    Ds[j * 132 + m]           = acc[mt][nt][0];
                    Ds[(j + 1) * 132 + m]     = acc[mt][nt][1];
                    Ds[j * 132 + m + 8]       = acc[mt][nt][2];
                    Ds[(j + 1) * 132 + m + 8] = acc[mt][nt][3];
                }
        }
        __syncthreads();
        emit_tiles(Ds, Eb, tid);
    }
}

// ---------------- launcher ----------------
extern "C" void kernel_launch(void* const* d_in, const int* in_sizes, int n_in,
                              void* d_out, int out_size)
{
    (void)in_sizes; (void)n_in; (void)out_size;
    const float* x = (const float*)d_in[0];     // (8,64,256,256)
    float* out     = (float*)d_out;             // (8,64,128,128)

    void *pB1, *pL1, *pB2, *pL2, *pX, *pT, *pC;
    cudaGetSymbolAddress(&pB1, g_B1c);
    cudaGetSymbolAddress(&pL1, g_L1c);
    cudaGetSymbolAddress(&pB2, g_B2c);
    cudaGetSymbolAddress(&pL2, g_L2c);
    cudaGetSymbolAddress(&pX,  g_Xb);
    cudaGetSymbolAddress(&pT,  g_Tb);
    cudaGetSymbolAddress(&pC,  g_Cb);
    char* B1 = (char*)pB1; char* L1 = (char*)pL1;
    char* B2 = (char*)pB2; char* L2 = (char*)pL2;
    char* Xb = (char*)pX;  char* Tb = (char*)pT; char* Cb = (char*)pC;
    char* Ub = Tb;   // U tiles reuse T space (T dead after pass2)

    cudaFuncSetAttribute(dht_pass<1, 256>, cudaFuncAttributeMaxDynamicSharedMemorySize, SMEM_BYTES);
    cudaFuncSetAttribute(dht_pass<2, 512>, cudaFuncAttributeMaxDynamicSharedMemorySize, SMEM_BYTES);
    cudaFuncSetAttribute(dht_pass<3, 128>, cudaFuncAttributeMaxDynamicSharedMemorySize, SMEM_BYTES);
    cudaFuncSetAttribute(dht_pass<4, 256>, cudaFuncAttributeMaxDynamicSharedMemorySize, SMEM_BYTES);

    gen_consts<<<768, 256>>>();
    cvt_x<<<16384, 256>>>(x);

    // pass1: T tiles = (X * B1^T)^T            M=131072, N=256, K=256
    dht_pass<1, 256><<<dim3(2, 1024, 1), 256, SMEM_BYTES>>>(Xb, B1, Tb, nullptr);
    // pass2: c tiles = L1 * Tsplit             M=128, N=128, K=512 per img
    dht_pass<2, 512><<<dim3(1, 1, 512), 256, SMEM_BYTES>>>(L1, Tb, Cb, nullptr);
    // pass3: U tiles = (c * B2^T)^T            M=128, N=256, K=128 per img
    dht_pass<3, 128><<<dim3(2, 1, 512), 256, SMEM_BYTES>>>(Cb, B2, Ub, nullptr);
    // pass4: y = L2 * Usplit                   M=128, N=128, K=256 per img
    dht_pass<4, 256><<<dim3(1, 1, 512), 256, SMEM_BYTES>>>(L2, Ub, nullptr, out);
}

// round 11
// speedup vs baseline: 2.6872x; 1.2186x over previous
#include <cuda_runtime.h>
#include <cuda_bf16.h>
#include <cstdint>

#define DI __device__ __forceinline__

// ============================================================================
// SpectralPoolNd: y = dht2_128( crop_center_128( dht2_256(x) ) )
// All operands pre-split into bf16 hi/lo in swizzled 32-K tile format.
// 4 GEMM passes, conflict-free cp.async fills, 3-stage pipeline, 2 CTAs/SM.
// ============================================================================

// Tile format: one K-chunk (32 k-values) of a 128-row operand = 16 KB:
//   [hi 8192 B][lo 8192 B], element (row, col) chunk addr = swz(row, col>>3),
//   byte within chunk = (col&7)*2.
DI uint32_t swz(int row, int kc) {
    return (uint32_t)(row * 64 + ((kc ^ ((row >> 1) & 3)) << 4));
}

// ---------------- device buffers (no allocations) ----------------
__device__ __align__(16) char g_B1c[2 * 8 * 16384];    // pass1 B tiles [nb][t]
__device__ __align__(16) char g_L1c[16 * 16384];       // pass2 A tiles [t]
__device__ __align__(16) char g_B2c[2 * 4 * 16384];    // pass3 B tiles [nb][t]
__device__ __align__(16) char g_L2c[8 * 16384];        // pass4 A tiles [t]
__device__ __align__(16) char g_Xb [1024 * 8 * 16384]; // x tiles [mb][t]   128MB
__device__ __align__(16) char g_Tb [512 * 16 * 16384]; // T tiles [img][t]  128MB (U aliases)
__device__ __align__(16) char g_Cb [512 * 4 * 16384];  // c tiles [img][t]   32MB

// ---------------- split helpers ----------------
DI uint32_t pk2(float a, float b) {
    __nv_bfloat162 t = __floats2bfloat162_rn(a, b);
    return *reinterpret_cast<uint32_t*>(&t);
}
DI void split8(const float4 v0, const float4 v1, uint4& H, uint4& L) {
    float e[8] = {v0.x, v0.y, v0.z, v0.w, v1.x, v1.y, v1.z, v1.w};
    float h[8], l[8];
    #pragma unroll
    for (int i = 0; i < 8; i++) {
        __nv_bfloat16 hb = __float2bfloat16_rn(e[i]);
        h[i] = __bfloat162float(hb);
        l[i] = e[i] - h[i];
    }
    H.x = pk2(h[0], h[1]); H.y = pk2(h[2], h[3]);
    H.z = pk2(h[4], h[5]); H.w = pk2(h[6], h[7]);
    L.x = pk2(l[0], l[1]); L.y = pk2(l[2], l[3]);
    L.z = pk2(l[4], l[5]); L.w = pk2(l[6], l[7]);
}

// ---------------- constant generator (exact integer phases) ----------------
__global__ void gen_consts() {
    int e = blockIdx.x * 256 + threadIdx.x;      // 0..196607
    float v; char* base; int row, col;
    if (e < 65536) {                             // B1c: [nb 2][t 8][row 128][col 32]
        int nb = e >> 15, r = e & 32767;
        int tile = r >> 12, rem = r & 4095; row = rem >> 5; col = rem & 31;
        int j = nb * 128 + row, k = tile * 32 + col;
        int jj = j & 127; float s = (j < 128) ? 1.f : -1.f;
        int ph = ((64 + jj) * k) & 255;
        float sn, cs; sincospif((float)ph / 128.f, &sn, &cs);
        v = cs + s * sn;
        base = g_B1c + (size_t)(nb * 8 + tile) * 16384;
    } else if (e < 131072) {                     // L1c: [t 16][row 128][col 32]
        int r = e - 65536;
        int tile = r >> 12, rem = r & 4095; row = rem >> 5; col = rem & 31;
        int kap = tile * 32 + col;
        int ph = ((64 + row) * (kap & 255)) & 255;
        float sn, cs; sincospif((float)ph / 128.f, &sn, &cs);
        v = (kap < 256) ? cs : sn;
        base = g_L1c + (size_t)tile * 16384;
    } else if (e < 163840) {                     // B2c: [nb 2][t 4][128][32]
        int r = e - 131072;
        int nb = r >> 14, r2 = r & 16383;
        int tile = r2 >> 12, rem = r2 & 4095; row = rem >> 5; col = rem & 31;
        int j = nb * 128 + row, k = tile * 32 + col;
        int jj = j & 127; float s = (j < 128) ? 1.f : -1.f;
        int ph = (jj * k) & 127;
        float sn, cs; sincospif((float)ph / 64.f, &sn, &cs);
        v = cs + s * sn;
        base = g_B2c + (size_t)(nb * 4 + tile) * 16384;
    } else {                                     // L2c: [t 8][128][32]
        int r = e - 163840;
        int tile = r >> 12, rem = r & 4095; row = rem >> 5; col = rem & 31;
        int k = tile * 32 + col;
        int ph = (row * (k & 127)) & 127;
        float sn, cs; sincospif((float)ph / 64.f, &sn, &cs);
        v = (k < 128) ? cs : sn;
        base = g_L2c + (size_t)tile * 16384;
    }
    __nv_bfloat16 hb = __float2bfloat16_rn(v);
    float hf = __bfloat162float(hb);
    __nv_bfloat16 lb = __float2bfloat16_rn(v - hf);
    char* p = base + swz(row, col >> 3) + (col & 7) * 2;
    *(__nv_bfloat16*)p = hb;
    *(__nv_bfloat16*)(p + 8192) = lb;
}

// ---------------- input converter: x (f32) -> split tiles ----------------
__global__ void cvt_x(const float* __restrict__ x) {
    int id = blockIdx.x * 256 + threadIdx.x;     // 0..4194303 chunk ids
    int kc = id & 3, row = (id >> 2) & 127, tile = id >> 9;   // tile 0..8191
    int mb = tile >> 3, t = tile & 7;
    const float* p = x + (size_t)(mb * 128 + row) * 256 + t * 32 + kc * 8;
    float4 v0 = *(const float4*)p, v1 = *(const float4*)(p + 4);
    uint4 H, L; split8(v0, v1, H, L);
    char* g = g_Xb + (size_t)tile * 16384 + swz(row, kc);
    *(uint4*)g = H;
    *(uint4*)(g + 8192) = L;
}

// ---------------- PTX ----------------
DI uint32_t smem_u32(const void* p) {
    uint32_t a;
    asm("{ .reg .u64 t; cvta.to.shared.u64 t, %1; cvt.u32.u64 %0, t; }"
        : "=r"(a) : "l"(p));
    return a;
}
#define CP_A16(dst, src)                                                       \
    asm volatile("cp.async.cg.shared.global [%0], [%1], 16;"                   \
                 :: "r"(dst), "l"(src))
#define CP_COMMIT() asm volatile("cp.async.commit_group;" ::: "memory")
#define CP_WAIT1()  asm volatile("cp.async.wait_group 1;" ::: "memory")
#define CP_WAIT0()  asm volatile("cp.async.wait_group 0;" ::: "memory")

DI void mma16(float* d, const uint32_t* a, uint32_t b0, uint32_t b1) {
    asm volatile(
        "mma.sync.aligned.m16n8k16.row.col.f32.bf16.bf16.f32 "
        "{%0,%1,%2,%3}, {%4,%5,%6,%7}, {%8,%9}, {%0,%1,%2,%3};\n"
        : "+f"(d[0]), "+f"(d[1]), "+f"(d[2]), "+f"(d[3])
        : "r"(a[0]), "r"(a[1]), "r"(a[2]), "r"(a[3]), "r"(b0), "r"(b1));
}
#define LDSM4(R, A)                                                            \
    asm volatile("ldmatrix.sync.aligned.m8n8.x4.shared.b16 {%0,%1,%2,%3}, [%4];" \
                 : "=r"((R)[0]), "=r"((R)[1]), "=r"((R)[2]), "=r"((R)[3])      \
                 : "r"(A))

// smem: 3 stages x 32KB: [AH 8K][AL 8K][BH 8K][BL 8K]; epilogue staging reuses.
constexpr int STAGE = 32768;
constexpr int SMEM_BYTES = 3 * STAGE;

// Conflict-free fill: pure 16KB memcpy per operand, any bijection works.
// Lane-consecutive 16B chunks -> zero smem bank conflicts on the STS side and
// fully coalesced 512B global segments per warp on the LDG side.
DI void fill_cp(uint32_t sdst, const char* __restrict__ sA,
                const char* __restrict__ sB, int tid) {
    const uint32_t o = (uint32_t)tid * 16;       // lanes consecutive 16B
    #pragma unroll
    for (int i = 0; i < 4; i++)                  // 4 x 4KB slabs
        CP_A16(sdst + o + i * 4096, sA + o + i * 4096);
    #pragma unroll
    for (int i = 0; i < 4; i++)
        CP_A16(sdst + 16384 + o + i * 4096, sB + o + i * 4096);
}

// emit a 128x128 f32 block (smem, stride 132) as 4 split-swizzled tiles
DI void emit_tiles(const float* __restrict__ Ds, char* __restrict__ gbase, int tid) {
    #pragma unroll 1
    for (int it = 0; it < 8; it++) {
        int c = it * 256 + tid;                  // 0..2047 chunk ids
        int r = c >> 4, cc = c & 15, tt = cc >> 2, kc = cc & 3;
        const float* p = Ds + r * 132 + cc * 8;
        float4 v0 = *(const float4*)p, v1 = *(const float4*)(p + 4);
        uint4 H, L; split8(v0, v1, H, L);
        char* g = gbase + tt * 16384 + swz(r, kc);
        *(uint4*)g = H;
        *(uint4*)(g + 8192) = L;
    }
}

// ---------------- main pass kernel ----------------
// C[128x128] = A[128,K] * B[128,K]^T, operands as split tiles; 3x bf16 MMA.
template <int PASS, int KTOT>
__global__ __launch_bounds__(256, 2) void dht_pass(
    const char* __restrict__ Asrc, const char* __restrict__ Bsrc,
    char* __restrict__ Ob, float* __restrict__ O0)
{
    extern __shared__ char smem[];
    const uint32_t sbu = smem_u32(smem);
    const int tid = threadIdx.x;
    const int lane = tid & 31, warp = tid >> 5;
    const int wm = warp & 3, wn = warp >> 2;
    constexpr int NT = KTOT / 32;

    const char* Ab; const char* Bb;
    char* Eb = nullptr; float* Eo = nullptr;
    if (PASS == 1) {
        const int mb = blockIdx.y, nb = blockIdx.x;
        Ab = Asrc + (size_t)mb * 131072;
        Bb = Bsrc + (size_t)nb * 131072;
        Eb = Ob + (size_t)(mb >> 1) * 262144 + (size_t)(nb * 8 + (mb & 1) * 4) * 16384;
    } else if (PASS == 2) {
        Ab = Asrc;
        Bb = Bsrc + (size_t)blockIdx.z * 262144;
        Eb = Ob + (size_t)blockIdx.z * 65536;
    } else if (PASS == 3) {
        const int nb = blockIdx.x;
        Ab = Asrc + (size_t)blockIdx.z * 65536;
        Bb = Bsrc + (size_t)nb * 65536;
        Eb = Ob + (size_t)blockIdx.z * 131072 + (size_t)nb * 65536;
    } else {
        Ab = Asrc;
        Bb = Bsrc + (size_t)blockIdx.z * 131072;
        Eo = O0 + (size_t)blockIdx.z * 16384;
    }

    float acc[2][8][4];
    #pragma unroll
    for (int mt = 0; mt < 2; mt++)
        #pragma unroll
        for (int nt = 0; nt < 8; nt++)
            #pragma unroll
            for (int q = 0; q < 4; q++) acc[mt][nt][q] = 0.0f;

    auto compute = [&](uint32_t sbase) {
        #pragma unroll
        for (int kk = 0; kk < 32; kk += 16) {
            const int c0 = kk >> 3;
            uint32_t aH[2][4], aL[2][4];
            #pragma unroll
            for (int mt = 0; mt < 2; mt++) {
                const int row = wm * 32 + mt * 16 + (lane & 15);
                const int ch  = c0 + (lane >> 4);
                const uint32_t off = swz(row, ch);
                LDSM4(aH[mt], sbase + off);
                LDSM4(aL[mt], sbase + 8192 + off);
            }
            #pragma unroll
            for (int nt = 0; nt < 4; nt++) {
                const int nrow = wn * 64 + nt * 16 + (lane & 7) + ((lane >> 4) << 3);
                const int ch   = c0 + ((lane >> 3) & 1);
                const uint32_t off = swz(nrow, ch);
                uint32_t bh[4], bl[4];
                LDSM4(bh, sbase + 16384 + off);
                LDSM4(bl, sbase + 24576 + off);
                #pragma unroll
                for (int mt = 0; mt < 2; mt++) {
                    mma16(acc[mt][nt * 2],     aH[mt], bh[0], bh[1]);
                    mma16(acc[mt][nt * 2],     aH[mt], bl[0], bl[1]);
                    mma16(acc[mt][nt * 2],     aL[mt], bh[0], bh[1]);
                    mma16(acc[mt][nt * 2 + 1], aH[mt], bh[2], bh[3]);
                    mma16(acc[mt][nt * 2 + 1], aH[mt], bl[2], bl[3]);
                    mma16(acc[mt][nt * 2 + 1], aL[mt], bh[2], bh[3]);
                }
            }
        }
    };

    // ---- 3-stage cp.async pipeline, one barrier per K-tile ----
    fill_cp(sbu,         Ab,         Bb,         tid); CP_COMMIT();
    fill_cp(sbu + STAGE, Ab + 16384, Bb + 16384, tid); CP_COMMIT();
    #pragma unroll 1
    for (int t = 0; t < NT; t++) {
        if (t + 1 < NT) { CP_WAIT1(); } else { CP_WAIT0(); }
        __syncthreads();
        if (t + 2 < NT) {
            const int s = (t + 2) % 3;
            fill_cp(sbu + s * STAGE, Ab + (size_t)(t + 2) * 16384,
                    Bb + (size_t)(t + 2) * 16384, tid);
            CP_COMMIT();
        }
        compute(sbu + (t % 3) * STAGE);
    }
    __syncthreads();

    // ---- epilogue ----
    if (PASS == 4) {
        // direct f32 row-major store to d_out
        #pragma unroll
        for (int mt = 0; mt < 2; mt++)
            #pragma unroll
            for (int nt = 0; nt < 8; nt++) {
                const int m = wm * 32 + mt * 16 + (lane >> 2);
                const int n = wn * 64 + nt * 8 + 2 * (lane & 3);
                *(float2*)&Eo[(size_t)m * 128 + n] =
                    make_float2(acc[mt][nt][0], acc[mt][nt][1]);
                *(float2*)&Eo[(size_t)(m + 8) * 128 + n] =
                    make_float2(acc[mt][nt][2], acc[mt][nt][3]);
            }
    } else {
        float* Ds = (float*)smem;
        if (PASS == 2) {
            // untransposed staging D[m][n]
            #pragma unroll
            for (int mt = 0; mt < 2; mt++)
                #pragma unroll
                for (int nt = 0; nt < 8; nt++) {
                    const int m = wm * 32 + mt * 16 + (lane >> 2);
                    const int n = wn * 64 + nt * 8 + 2 * (lane & 3);
                    *(float2*)&Ds[m * 132 + n] =
                        make_float2(acc[mt][nt][0], acc[mt][nt][1]);
                    *(float2*)&Ds[(m + 8) * 132 + n] =
                        make_float2(acc[mt][nt][2], acc[mt][nt][3]);
                }
        } else {
            // transposed staging D[j][m]  (j = output row of T_t/U_t)
            #pragma unroll
            for (int mt = 0; mt < 2; mt++)
                #pragma unroll
                for (int nt = 0; nt < 8; nt++) {
                    const int m = wm * 32 + mt * 16 + (lane >> 2);
                    const int j = wn * 64 + nt * 8 + 2 * (lane & 3);
                    Ds[j * 132 + m]           = acc[mt][nt][0];
                    Ds[(j + 1) * 132 + m]     = acc[mt][nt][1];
                    Ds[j * 132 + m + 8]       = acc[mt][nt][2];
                    Ds[(j + 1) * 132 + m + 8] = acc[mt][nt][3];
                }
        }
        __syncthreads();
        emit_tiles(Ds, Eb, tid);
    }
}

// ---------------- launcher ----------------
extern "C" void kernel_launch(void* const* d_in, const int* in_sizes, int n_in,
                              void* d_out, int out_size)
{
    (void)in_sizes; (void)n_in; (void)out_size;
    const float* x = (const float*)d_in[0];     // (8,64,256,256)
    float* out     = (float*)d_out;             // (8,64,128,128)

    void *pB1, *pL1, *pB2, *pL2, *pX, *pT, *pC;
    cudaGetSymbolAddress(&pB1, g_B1c);
    cudaGetSymbolAddress(&pL1, g_L1c);
    cudaGetSymbolAddress(&pB2, g_B2c);
    cudaGetSymbolAddress(&pL2, g_L2c);
    cudaGetSymbolAddress(&pX,  g_Xb);
    cudaGetSymbolAddress(&pT,  g_Tb);
    cudaGetSymbolAddress(&pC,  g_Cb);
    char* B1 = (char*)pB1; char* L1 = (char*)pL1;
    char* B2 = (char*)pB2; char* L2 = (char*)pL2;
    char* Xb = (char*)pX;  char* Tb = (char*)pT; char* Cb = (char*)pC;
    char* Ub = Tb;   // U tiles reuse T space (T dead after pass2)

    cudaFuncSetAttribute(dht_pass<1, 256>, cudaFuncAttributeMaxDynamicSharedMemorySize, SMEM_BYTES);
    cudaFuncSetAttribute(dht_pass<2, 512>, cudaFuncAttributeMaxDynamicSharedMemorySize, SMEM_BYTES);
    cudaFuncSetAttribute(dht_pass<3, 128>, cudaFuncAttributeMaxDynamicSharedMemorySize, SMEM_BYTES);
    cudaFuncSetAttribute(dht_pass<4, 256>, cudaFuncAttributeMaxDynamicSharedMemorySize, SMEM_BYTES);

    gen_consts<<<768, 256>>>();
    cvt_x<<<16384, 256>>>(x);

    // pass1: T tiles = (X * B1^T)^T            M=131072, N=256, K=256
    dht_pass<1, 256><<<dim3(2, 1024, 1), 256, SMEM_BYTES>>>(Xb, B1, Tb, nullptr);
    // pass2: c tiles = L1 * Tsplit             M=128, N=128, K=512 per img
    dht_pass<2, 512><<<dim3(1, 1, 512), 256, SMEM_BYTES>>>(L1, Tb, Cb, nullptr);
    // pass3: U tiles = (c * B2^T)^T            M=128, N=256, K=128 per img
    dht_pass<3, 128><<<dim3(2, 1, 512), 256, SMEM_BYTES>>>(Cb, B2, Ub, nullptr);
    // pass4: y = L2 * Usplit                   M=128, N=128, K=256 per img
    dht_pass<4, 256><<<dim3(1, 1, 512), 256, SMEM_BYTES>>>(L2, Ub, nullptr, out);
}

// round 12
// speedup vs baseline: 3.9986x; 1.4880x over previous
#include <cuda_runtime.h>
#include <cuda_bf16.h>
#include <cstdint>

#define DI __device__ __forceinline__

// ============================================================================
// SpectralPoolNd: y = dht2_128( crop_center_128( dht2_256(x) ) )
// Parity-folded DHT: every contraction halved via g(f,k+N/2)=(-1)^f g(f,k).
// bf16 hi/lo 3-term split on mma.sync.m16n8k16, swizzled 32-K tiles,
// cp.async 3-stage pipeline, folds computed free in epilogues.
// ============================================================================

DI uint32_t swz(int row, int kc) {
    return (uint32_t)(row * 64 + ((kc ^ ((row >> 1) & 3)) << 4));
}

// ---------------- device buffers (no allocations) ----------------
__device__ __align__(16) char g_B1f[2 * 4 * 16384];   // pass1 B [nb][4 tiles]
__device__ __align__(16) char g_L1f[2 * 8 * 16384];   // pass2 B [par][8]
__device__ __align__(16) char g_B2f[2 * 2 * 16384];   // pass3 B [nb][2]
__device__ __align__(16) char g_L2f[2 * 4 * 16384];   // pass4 B [par][4]
__device__ __align__(16) char g_Xb [1024 * 8 * 16384];// x E/O tiles [mb][E4|O4]
__device__ __align__(16) char g_Tb [512 * 16 * 16384];// pass2 A tiles [img][E8|O8]; pass4 A aliases
__device__ __align__(16) char g_Cb [512 * 4 * 16384]; // pass3 A tiles [img][E2|O2]

// ---------------- split helpers ----------------
DI uint32_t pk2(float a, float b) {
    __nv_bfloat162 t = __floats2bfloat162_rn(a, b);
    return *reinterpret_cast<uint32_t*>(&t);
}
DI void split8(const float4 v0, const float4 v1, uint4& H, uint4& L) {
    float e[8] = {v0.x, v0.y, v0.z, v0.w, v1.x, v1.y, v1.z, v1.w};
    float h[8], l[8];
    #pragma unroll
    for (int i = 0; i < 8; i++) {
        __nv_bfloat16 hb = __float2bfloat16_rn(e[i]);
        h[i] = __bfloat162float(hb);
        l[i] = e[i] - h[i];
    }
    H.x = pk2(h[0], h[1]); H.y = pk2(h[2], h[3]);
    H.z = pk2(h[4], h[5]); H.w = pk2(h[6], h[7]);
    L.x = pk2(l[0], l[1]); L.y = pk2(l[2], l[3]);
    L.z = pk2(l[4], l[5]); L.w = pk2(l[6], l[7]);
}
DI float4 f4add(float4 a, float4 b) {
    return make_float4(a.x + b.x, a.y + b.y, a.z + b.z, a.w + b.w);
}
DI float4 f4sub(float4 a, float4 b) {
    return make_float4(a.x - b.x, a.y - b.y, a.z - b.z, a.w - b.w);
}

// ---------------- constant generator (exact integer phases) ----------------
// B1f[nb]: rows n (128): n<64 cas+_{64+j}, n>=64 cas-_{64+j}, j=2(n&63)+nb; K=w 0..127
// L1f[par]: rows me (64): kap<128 cos th(64+2me+par,kap); kap>=128 sin(.,kap-128)
// B2f[nb]: rows n (128): cas2+-_{jw}(vl), jw=2(n&63)+nb; K=vl 0..63
// L2f[par]: rows me (64): kap<64 cos ph(2me+par,kap); kap>=64 sin(.,kap-64)
__global__ void gen_consts() {
    int e = blockIdx.x * 256 + threadIdx.x;      // 0..98303
    float v; char* base; int row; int col;       // col = K index within group
    int tiles16 = 0;
    if (e < 32768) {                             // B1f
        int nb = e >> 14, r = e & 16383;
        int n = r >> 7, w = r & 127;
        int j = 2 * (n & 63) + nb, f = 64 + j;
        float s = (n < 64) ? 1.f : -1.f;
        int ph = (f * w) & 255;
        float sn, cs; sincospif((float)ph / 128.f, &sn, &cs);
        v = cs + s * sn;
        base = g_B1f + (size_t)nb * 65536; row = n; col = w;
    } else if (e < 65536) {                      // L1f
        int r = e - 32768;
        int par = r >> 14, r2 = r & 16383;
        int me = r2 >> 8, kap = r2 & 255;
        int f = 64 + 2 * me + par;
        if (kap < 128) {
            int ph = (f * kap) & 255;
            float sn, cs; sincospif((float)ph / 128.f, &sn, &cs); v = cs;
        } else {
            int ph = (f * (kap - 128)) & 255;
            float sn, cs; sincospif((float)ph / 128.f, &sn, &cs); v = sn;
        }
        base = g_L1f + (size_t)par * 131072; row = me; col = kap;
    } else if (e < 81920) {                      // B2f
        int r = e - 65536;
        int nb = r >> 13, r2 = r & 8191;
        int n = r2 >> 6, vl = r2 & 63;
        int jw = 2 * (n & 63) + nb;
        float s = (n < 64) ? 1.f : -1.f;
        int ph = (jw * vl) & 127;
        float sn, cs; sincospif((float)ph / 64.f, &sn, &cs);
        v = cs + s * sn;
        base = g_B2f + (size_t)nb * 32768; row = n; col = vl;
    } else {                                     // L2f
        int r = e - 81920;
        int par = r >> 13, r2 = r & 8191;
        int me = r2 >> 7, kap = r2 & 127;
        int f = 2 * me + par;
        if (kap < 64) {
            int ph = (f * kap) & 127;
            float sn, cs; sincospif((float)ph / 64.f, &sn, &cs); v = cs;
        } else {
            int ph = (f * (kap - 64)) & 127;
            float sn, cs; sincospif((float)ph / 64.f, &sn, &cs); v = sn;
        }
        base = g_L2f + (size_t)par * 65536; row = me; col = kap;
    }
    (void)tiles16;
    __nv_bfloat16 hb = __float2bfloat16_rn(v);
    float hf = __bfloat162float(hb);
    __nv_bfloat16 lb = __float2bfloat16_rn(v - hf);
    char* p = base + (size_t)(col >> 5) * 16384 + swz(row, (col >> 3) & 3) + (col & 7) * 2;
    *(__nv_bfloat16*)p = hb;
    *(__nv_bfloat16*)(p + 8192) = lb;
}

// ---------------- input converter: x -> E/O folded tiles ----------------
// mb = img*2 + half; tile rows r: r<64 -> h=64*half+r ; r>=64 -> h=64*half+64+r
// E[w]=x[h][w]+x[h][w+128], O=diff (w 0..127).
__global__ void cvt_x(const float* __restrict__ x) {
    int id = blockIdx.x * 256 + threadIdx.x;     // 2097152 chunk-pairs
    int kc = id & 3, r = (id >> 2) & 127, t = (id >> 9) & 3, mb = id >> 11;
    int img = mb >> 1, half = mb & 1;
    int h = 64 * half + ((r < 64) ? r : 64 + r);
    int w = t * 32 + kc * 8;
    const float* p = x + (size_t)img * 65536 + (size_t)h * 256 + w;
    float4 a0 = *(const float4*)p,        a1 = *(const float4*)(p + 4);
    float4 b0 = *(const float4*)(p + 128), b1 = *(const float4*)(p + 132);
    uint4 H, L;
    char* gE = g_Xb + (size_t)mb * 131072 + (size_t)t * 16384 + swz(r, kc);
    split8(f4add(a0, b0), f4add(a1, b1), H, L);
    *(uint4*)gE = H; *(uint4*)(gE + 8192) = L;
    char* gO = gE + 4 * 16384;
    split8(f4sub(a0, b0), f4sub(a1, b1), H, L);
    *(uint4*)gO = H; *(uint4*)(gO + 8192) = L;
}

// ---------------- PTX ----------------
DI uint32_t smem_u32(const void* p) {
    uint32_t a;
    asm("{ .reg .u64 t; cvta.to.shared.u64 t, %1; cvt.u32.u64 %0, t; }"
        : "=r"(a) : "l"(p));
    return a;
}
#define CP_A16(dst, src)                                                       \
    asm volatile("cp.async.cg.shared.global [%0], [%1], 16;"                   \
                 :: "r"(dst), "l"(src))
#define CP_COMMIT() asm volatile("cp.async.commit_group;" ::: "memory")
#define CP_WAIT1()  asm volatile("cp.async.wait_group 1;" ::: "memory")
#define CP_WAIT0()  asm volatile("cp.async.wait_group 0;" ::: "memory")

DI void mma16(float* d, const uint32_t* a, uint32_t b0, uint32_t b1) {
    asm volatile(
        "mma.sync.aligned.m16n8k16.row.col.f32.bf16.bf16.f32 "
        "{%0,%1,%2,%3}, {%4,%5,%6,%7}, {%8,%9}, {%0,%1,%2,%3};\n"
        : "+f"(d[0]), "+f"(d[1]), "+f"(d[2]), "+f"(d[3])
        : "r"(a[0]), "r"(a[1]), "r"(a[2]), "r"(a[3]), "r"(b0), "r"(b1));
}
#define LDSM4(R, A)                                                            \
    asm volatile("ldmatrix.sync.aligned.m8n8.x4.shared.b16 {%0,%1,%2,%3}, [%4];" \
                 : "=r"((R)[0]), "=r"((R)[1]), "=r"((R)[2]), "=r"((R)[3])      \
                 : "r"(A))

constexpr int STAGE = 32768;
constexpr int SMEM_BYTES = 3 * STAGE;   // 96KB; epilogue staging reuses (<=67.6KB)

// Conflict-free fill; BHALF copies only B rows 0..63 (hi 0..4K, lo 8..12K).
template <bool BHALF>
DI void fill_cp(uint32_t sdst, const char* __restrict__ sA,
                const char* __restrict__ sB, int tid) {
    const uint32_t o = (uint32_t)tid * 16;
    #pragma unroll
    for (int i = 0; i < 4; i++)
        CP_A16(sdst + o + i * 4096, sA + o + i * 4096);
    if (BHALF) {
        CP_A16(sdst + 16384 + o,        sB + o);
        CP_A16(sdst + 16384 + o + 8192, sB + o + 8192);
    } else {
        #pragma unroll
        for (int i = 0; i < 4; i++)
            CP_A16(sdst + 16384 + o + i * 4096, sB + o + i * 4096);
    }
}

// ---------------- main pass kernel ----------------
template <int PASS>
__global__ __launch_bounds__(256, 2) void dht_pass(
    const char* __restrict__ Asrc, const char* __restrict__ Bsrc,
    char* __restrict__ Ob, float* __restrict__ O0)
{
    constexpr int  NT   = (PASS == 1) ? 4 : (PASS == 2) ? 8 : (PASS == 3) ? 2 : 4;
    constexpr bool NH   = (PASS == 2 || PASS == 4);   // N=64 swapped passes
    constexpr int  NACC = NH ? 4 : 8;
    constexpr int  WNW  = NH ? 32 : 64;

    extern __shared__ char smem[];
    const uint32_t sbu = smem_u32(smem);
    const int tid = threadIdx.x;
    const int lane = tid & 31, warp = tid >> 5;
    const int wm = warp & 3, wn = warp >> 2;

    const int g0  = blockIdx.x;                  // nb or par
    const int img = (PASS == 1) ? ((int)blockIdx.y >> 1) : (int)blockIdx.z;
    const int half = (PASS == 1) ? ((int)blockIdx.y & 1) : 0;

    const char* Ab; const char* Bb;
    char* Eb = nullptr; float* Eo = nullptr;
    if (PASS == 1) {
        Ab = Asrc + (size_t)blockIdx.y * 131072 + (size_t)g0 * 65536;
        Bb = Bsrc + (size_t)g0 * 65536;
        Eb = Ob + (size_t)img * 262144;
    } else if (PASS == 2) {
        Ab = Asrc + (size_t)img * 262144 + (size_t)g0 * 131072;
        Bb = Bsrc + (size_t)g0 * 131072;
        Eb = Ob + (size_t)img * 65536;
    } else if (PASS == 3) {
        Ab = Asrc + (size_t)img * 65536 + (size_t)g0 * 32768;
        Bb = Bsrc + (size_t)g0 * 32768;
        Eb = Ob + (size_t)img * 131072;
    } else {
        Ab = Asrc + (size_t)img * 131072 + (size_t)g0 * 65536;
        Bb = Bsrc + (size_t)g0 * 65536;
        Eo = O0 + (size_t)img * 16384;
    }

    float acc[2][NACC][4];
    #pragma unroll
    for (int mt = 0; mt < 2; mt++)
        #pragma unroll
        for (int q = 0; q < NACC; q++)
            #pragma unroll
            for (int e = 0; e < 4; e++) acc[mt][q][e] = 0.0f;

    auto compute = [&](uint32_t sbase) {
        #pragma unroll
        for (int kk = 0; kk < 32; kk += 16) {
            const int c0 = kk >> 3;
            uint32_t aH[2][4], aL[2][4];
            #pragma unroll
            for (int mt = 0; mt < 2; mt++) {
                const int row = wm * 32 + mt * 16 + (lane & 15);
                const int ch  = c0 + (lane >> 4);
                const uint32_t off = swz(row, ch);
                LDSM4(aH[mt], sbase + off);
                LDSM4(aL[mt], sbase + 8192 + off);
            }
            #pragma unroll
            for (int nt = 0; nt < NACC / 2; nt++) {
                const int nrow = wn * WNW + nt * 16 + (lane & 7) + ((lane >> 4) << 3);
                const int ch   = c0 + ((lane >> 3) & 1);
                const uint32_t off = swz(nrow, ch);
                uint32_t bh[4], bl[4];
                LDSM4(bh, sbase + 16384 + off);
                LDSM4(bl, sbase + 24576 + off);
                #pragma unroll
                for (int mt = 0; mt < 2; mt++) {
                    mma16(acc[mt][nt * 2],     aH[mt], bh[0], bh[1]);
                    mma16(acc[mt][nt * 2],     aH[mt], bl[0], bl[1]);
                    mma16(acc[mt][nt * 2],     aL[mt], bh[0], bh[1]);
                    mma16(acc[mt][nt * 2 + 1], aH[mt], bh[2], bh[3]);
                    mma16(acc[mt][nt * 2 + 1], aH[mt], bl[2], bl[3]);
                    mma16(acc[mt][nt * 2 + 1], aL[mt], bh[2], bh[3]);
                }
            }
        }
    };

    // ---- 3-stage cp.async pipeline ----
    fill_cp<NH>(sbu,         Ab,         Bb,         tid); CP_COMMIT();
    fill_cp<NH>(sbu + STAGE, Ab + 16384, Bb + 16384, tid); CP_COMMIT();
    #pragma unroll 1
    for (int t = 0; t < NT; t++) {
        if (t + 1 < NT) { CP_WAIT1(); } else { CP_WAIT0(); }
        __syncthreads();
        if (t + 2 < NT) {
            const int s = (t + 2) % 3;
            fill_cp<NH>(sbu + s * STAGE, Ab + (size_t)(t + 2) * 16384,
                        Bb + (size_t)(t + 2) * 16384, tid);
            CP_COMMIT();
        }
        compute(sbu + (t % 3) * STAGE);
    }
    __syncthreads();

    // ---- epilogue: transposed staging Ds[n][i] = C[i][n] ----
    float* Ds = (float*)smem;
    #pragma unroll
    for (int mt = 0; mt < 2; mt++)
        #pragma unroll
        for (int q = 0; q < NACC; q++) {
            const int n = wn * WNW + q * 8 + 2 * (lane & 3);
            const int i = wm * 32 + mt * 16 + (lane >> 2);
            Ds[n * 132 + i]           = acc[mt][q][0];
            Ds[(n + 1) * 132 + i]     = acc[mt][q][1];
            Ds[n * 132 + i + 8]       = acc[mt][q][2];
            Ds[(n + 1) * 132 + i + 8] = acc[mt][q][3];
        }
    __syncthreads();

    if (PASS == 1) {
        // fold h: pair rows (rf, rf+64) -> hl = 64*half+rf; emit E->tiles0-7, O->8-15
        #pragma unroll 1
        for (int it = 0; it < 4; it++) {
            int c = it * 256 + tid;
            int n = c >> 3, rf8 = (c & 7) * 8;
            const float* pr = Ds + n * 132 + rf8;
            float4 a0 = *(const float4*)pr,        a1 = *(const float4*)(pr + 4);
            float4 b0 = *(const float4*)(pr + 64), b1 = *(const float4*)(pr + 68);
            int v = 2 * (n & 63) + g0, var = n >> 6;
            int hl = 64 * half + rf8;
            int tile = var * 4 + (hl >> 5);
            uint32_t sw = swz(v, (hl >> 3) & 3);
            uint4 H, L;
            char* gE = Eb + (size_t)tile * 16384 + sw;
            split8(f4add(a0, b0), f4add(a1, b1), H, L);
            *(uint4*)gE = H; *(uint4*)(gE + 8192) = L;
            char* gO = Eb + (size_t)(8 + tile) * 16384 + sw;
            split8(f4sub(a0, b0), f4sub(a1, b1), H, L);
            *(uint4*)gO = H; *(uint4*)(gO + 8192) = L;
        }
    } else if (PASS == 2) {
        // fold v: E3/O3, rows m = 2*me+par; E tiles 0-1, O tiles 2-3
        #pragma unroll 1
        for (int it = 0; it < 2; it++) {
            int c = it * 256 + tid;
            int me = c >> 3, vl8 = (c & 7) * 8;
            const float* pr = Ds + me * 132 + vl8;
            float4 a0 = *(const float4*)pr,        a1 = *(const float4*)(pr + 4);
            float4 b0 = *(const float4*)(pr + 64), b1 = *(const float4*)(pr + 68);
            int m = 2 * me + g0;
            int tile = vl8 >> 5;
            uint32_t sw = swz(m, (vl8 >> 3) & 3);
            uint4 H, L;
            char* gE = Eb + (size_t)tile * 16384 + sw;
            split8(f4add(a0, b0), f4add(a1, b1), H, L);
            *(uint4*)gE = H; *(uint4*)(gE + 8192) = L;
            char* gO = Eb + (size_t)(2 + tile) * 16384 + sw;
            split8(f4sub(a0, b0), f4sub(a1, b1), H, L);
            *(uint4*)gO = H; *(uint4*)(gO + 8192) = L;
        }
    } else if (PASS == 3) {
        // fold m: E4/O4, rows jw; E tiles 0-3, O tiles 4-7 (2 per variant)
        #pragma unroll 1
        for (int it = 0; it < 4; it++) {
            int c = it * 256 + tid;
            int n = c >> 3, ml8 = (c & 7) * 8;
            const float* pr = Ds + n * 132 + ml8;
            float4 a0 = *(const float4*)pr,        a1 = *(const float4*)(pr + 4);
            float4 b0 = *(const float4*)(pr + 64), b1 = *(const float4*)(pr + 68);
            int jw = 2 * (n & 63) + g0, var = n >> 6;
            int tile = var * 2 + (ml8 >> 5);
            uint32_t sw = swz(jw, (ml8 >> 3) & 3);
            uint4 H, L;
            char* gE = Eb + (size_t)tile * 16384 + sw;
            split8(f4add(a0, b0), f4add(a1, b1), H, L);
            *(uint4*)gE = H; *(uint4*)(gE + 8192) = L;
            char* gO = Eb + (size_t)(4 + tile) * 16384 + sw;
            split8(f4sub(a0, b0), f4sub(a1, b1), H, L);
            *(uint4*)gO = H; *(uint4*)(gO + 8192) = L;
        }
    } else {
        // direct f32 store: y[2*me+par][jw]
        #pragma unroll 1
        for (int it = 0; it < 8; it++) {
            int c = it * 256 + tid;              // 2048 float4s
            int me = c >> 5, j4 = (c & 31) * 4;
            float4 v = *(const float4*)(Ds + me * 132 + j4);
            *(float4*)(Eo + (size_t)(2 * me + g0) * 128 + j4) = v;
        }
    }
}

// ---------------- launcher ----------------
extern "C" void kernel_launch(void* const* d_in, const int* in_sizes, int n_in,
                              void* d_out, int out_size)
{
    (void)in_sizes; (void)n_in; (void)out_size;
    const float* x = (const float*)d_in[0];     // (8,64,256,256)
    float* out     = (float*)d_out;             // (8,64,128,128)

    void *pB1, *pL1, *pB2, *pL2, *pX, *pT, *pC;
    cudaGetSymbolAddress(&pB1, g_B1f);
    cudaGetSymbolAddress(&pL1, g_L1f);
    cudaGetSymbolAddress(&pB2, g_B2f);
    cudaGetSymbolAddress(&pL2, g_L2f);
    cudaGetSymbolAddress(&pX,  g_Xb);
    cudaGetSymbolAddress(&pT,  g_Tb);
    cudaGetSymbolAddress(&pC,  g_Cb);
    char* B1 = (char*)pB1; char* L1 = (char*)pL1;
    char* B2 = (char*)pB2; char* L2 = (char*)pL2;
    char* Xb = (char*)pX;  char* Tb = (char*)pT; char* Cb = (char*)pC;
    char* Ub = Tb;   // pass4 A tiles alias Tb (Tb dead after pass2)

    cudaFuncSetAttribute(dht_pass<1>, cudaFuncAttributeMaxDynamicSharedMemorySize, SMEM_BYTES);
    cudaFuncSetAttribute(dht_pass<2>, cudaFuncAttributeMaxDynamicSharedMemorySize, SMEM_BYTES);
    cudaFuncSetAttribute(dht_pass<3>, cudaFuncAttributeMaxDynamicSharedMemorySize, SMEM_BYTES);
    cudaFuncSetAttribute(dht_pass<4>, cudaFuncAttributeMaxDynamicSharedMemorySize, SMEM_BYTES);

    gen_consts<<<384, 256>>>();
    cvt_x<<<8192, 256>>>(x);

    // pass1: T parity groups      M=131072, N=128, K=128, x2 nb
    dht_pass<1><<<dim3(2, 1024, 1), 256, SMEM_BYTES>>>(Xb, B1, Tb, nullptr);
    // pass2: c^T parity groups    M=128(v), N=64, K=256, x2 par per img
    dht_pass<2><<<dim3(2, 1, 512), 256, SMEM_BYTES>>>(Tb, L1, Cb, nullptr);
    // pass3: u parity groups      M=128(m), N=128, K=64, x2 nb per img
    dht_pass<3><<<dim3(2, 1, 512), 256, SMEM_BYTES>>>(Cb, B2, Ub, nullptr);
    // pass4: y parity groups      M=128(jw), N=64, K=128, x2 par per img
    dht_pass<4><<<dim3(2, 1, 512), 256, SMEM_BYTES>>>(Ub, L2, nullptr, out);
}